// round 1
// baseline (speedup 1.0000x reference)
#include <cuda_runtime.h>
#include <cstddef>

// ---------------------------------------------------------------------------
// NeuralODE: Dopri5 fixed-step integrator over a 3-layer MLP vector field.
// B=1024, D=256, H=512, T=11, SUBSTEPS=4  ->  40 RK steps, 6 MLP evals each.
// All fp32. Sequence of GEMM launches captured into one CUDA graph.
// ---------------------------------------------------------------------------

#define BB 1024
#define DD 256
#define HH 512
#define N_STEPS 40          // (T-1)*SUBSTEPS
#define HSTEP 0.25f         // T_TOTAL/(T-1)/SUBSTEPS = 10/10/4

// Scratch (static device globals; no allocation allowed)
__device__ float g_y [BB * DD];
__device__ float g_k [6][BB * DD];
__device__ float g_h1[BB * HH];
__device__ float g_h2[BB * HH];

struct Combine {
    const float* k[5];
    float        c[5];
    int          n;
};

// C[M,N] = act(A[M,K] @ W[N,K]^T + bias), A optionally combined on the fly:
//   Aeff[i] = A0[i] + sum_j c[j]*k[j][i]
// Shapes always divide tile sizes (M=1024, K/N in {256,512}).
template<int BM, int BN, bool RELU>
__global__ void gemm_bias_act(const float* __restrict__ A0, Combine cmb,
                              const float* __restrict__ W,
                              const float* __restrict__ bias,
                              float* __restrict__ C, int K, int N)
{
    constexpr int BK = 16;
    constexpr int TX = BN / 4;
    constexpr int TY = BM / 4;
    constexpr int NT = TX * TY;

    __shared__ float As[BM][BK + 1];
    __shared__ float Ws[BN][BK + 1];

    const int tx  = threadIdx.x;
    const int ty  = threadIdx.y;
    const int tid = ty * TX + tx;
    const int m0  = blockIdx.y * BM;
    const int n0  = blockIdx.x * BN;

    float acc[4][4];
    #pragma unroll
    for (int r = 0; r < 4; r++)
        #pragma unroll
        for (int c = 0; c < 4; c++) acc[r][c] = 0.0f;

    for (int kt = 0; kt < K; kt += BK) {
        // ---- load A tile (with optional RK-stage combine) ----
        #pragma unroll
        for (int idx = tid; idx < BM * (BK / 4); idx += NT) {
            int r  = idx / (BK / 4);
            int c4 = (idx % (BK / 4)) * 4;
            size_t off = (size_t)(m0 + r) * K + kt + c4;
            float4 v = *(const float4*)(A0 + off);
            for (int j = 0; j < cmb.n; j++) {
                float4 kv = *(const float4*)(cmb.k[j] + off);
                float cj = cmb.c[j];
                v.x += cj * kv.x; v.y += cj * kv.y;
                v.z += cj * kv.z; v.w += cj * kv.w;
            }
            As[r][c4 + 0] = v.x; As[r][c4 + 1] = v.y;
            As[r][c4 + 2] = v.z; As[r][c4 + 3] = v.w;
        }
        // ---- load W tile ----
        #pragma unroll
        for (int idx = tid; idx < BN * (BK / 4); idx += NT) {
            int r  = idx / (BK / 4);
            int c4 = (idx % (BK / 4)) * 4;
            float4 v = *(const float4*)(W + (size_t)(n0 + r) * K + kt + c4);
            Ws[r][c4 + 0] = v.x; Ws[r][c4 + 1] = v.y;
            Ws[r][c4 + 2] = v.z; Ws[r][c4 + 3] = v.w;
        }
        __syncthreads();

        #pragma unroll
        for (int k = 0; k < BK; k++) {
            float a[4], b[4];
            #pragma unroll
            for (int r = 0; r < 4; r++) a[r] = As[ty * 4 + r][k];
            #pragma unroll
            for (int c = 0; c < 4; c++) b[c] = Ws[tx * 4 + c][k];
            #pragma unroll
            for (int r = 0; r < 4; r++)
                #pragma unroll
                for (int c = 0; c < 4; c++)
                    acc[r][c] += a[r] * b[c];
        }
        __syncthreads();
    }

    #pragma unroll
    for (int c = 0; c < 4; c++) {
        float bv = bias[n0 + tx * 4 + c];
        #pragma unroll
        for (int r = 0; r < 4; r++) {
            float v = acc[r][c] + bv;
            if (RELU) v = fmaxf(v, 0.0f);
            C[(size_t)(m0 + ty * 4 + r) * N + n0 + tx * 4 + c] = v;
        }
    }
}

// y += h*(b1*k1 + b3*k3 + b4*k4 + b5*k5 + b6*k6); optionally emit to output.
__global__ void rk_finalize(float* __restrict__ y,
                            const float* __restrict__ k1,
                            const float* __restrict__ k3,
                            const float* __restrict__ k4,
                            const float* __restrict__ k5,
                            const float* __restrict__ k6,
                            float* __restrict__ out, int t)
{
    int i = blockIdx.x * blockDim.x + threadIdx.x;
    const float c1 = HSTEP * (float)(35.0 / 384.0);
    const float c3 = HSTEP * (float)(500.0 / 1113.0);
    const float c4 = HSTEP * (float)(125.0 / 192.0);
    const float c5 = HSTEP * (float)(-2187.0 / 6784.0);
    const float c6 = HSTEP * (float)(11.0 / 84.0);
    float v = y[i] + c1 * k1[i] + c3 * k3[i] + c4 * k4[i] + c5 * k5[i] + c6 * k6[i];
    y[i] = v;
    if (out) {
        int b = i >> 8;         // D = 256
        int d = i & 255;
        out[(size_t)b * (10 * DD) + t * DD + d] = v;
    }
}

extern "C" void kernel_launch(void* const* d_in, const int* in_sizes, int n_in,
                              void* d_out, int out_size)
{
    (void)in_sizes; (void)n_in; (void)out_size;
    const float* x0 = (const float*)d_in[0];
    // d_in[1] is T (int32, always 11) — integration length baked into the graph.
    const float* W1 = (const float*)d_in[2];
    const float* b1 = (const float*)d_in[3];
    const float* W2 = (const float*)d_in[4];
    const float* b2 = (const float*)d_in[5];
    const float* W3 = (const float*)d_in[6];
    const float* b3 = (const float*)d_in[7];
    float* out = (float*)d_out;

    float *y, *h1, *h2, *kbase;
    cudaGetSymbolAddress((void**)&y,     g_y);
    cudaGetSymbolAddress((void**)&h1,    g_h1);
    cudaGetSymbolAddress((void**)&h2,    g_h2);
    cudaGetSymbolAddress((void**)&kbase, g_k);
    float* k[6];
    for (int j = 0; j < 6; j++) k[j] = kbase + (size_t)j * BB * DD;

    // y = x0[:,0,:]
    cudaMemcpyAsync(y, x0, sizeof(float) * BB * DD, cudaMemcpyDeviceToDevice);

    // Dopri5 stage coefficients (times h)
    const double A2[] = {1.0/5.0};
    const double A3[] = {3.0/40.0, 9.0/40.0};
    const double A4[] = {44.0/45.0, -56.0/15.0, 32.0/9.0};
    const double A5[] = {19372.0/6561.0, -25360.0/2187.0, 64448.0/6561.0, -212.0/729.0};
    const double A6[] = {9017.0/3168.0, -355.0/33.0, 46732.0/5247.0, 49.0/176.0, -5103.0/18656.0};
    const double* Arows[5] = {A2, A3, A4, A5, A6};

    const dim3 thr1(16, 16);                 // 64x64 tiles, 256 thr
    const dim3 thr3(16, 8);                  // 32x64 tiles, 128 thr
    const dim3 grdL1(HH / 64, BB / 64);      // 8 x 16 = 128 blocks
    const dim3 grdL2(HH / 64, BB / 64);      // 128 blocks
    const dim3 grdL3(DD / 64, BB / 32);      // 4 x 32 = 128 blocks

    Combine cnone; cnone.n = 0;

    for (int step = 0; step < N_STEPS; step++) {
        for (int s = 0; s < 6; s++) {
            Combine cmb; cmb.n = 0;
            if (s > 0) {
                const double* row = Arows[s - 1];
                cmb.n = s;
                for (int j = 0; j < s; j++) {
                    cmb.k[j] = k[j];
                    cmb.c[j] = (float)((double)HSTEP * row[j]);
                }
            }
            // layer 1: [B,D] -> [B,H], relu
            gemm_bias_act<64, 64, true ><<<grdL1, thr1>>>(y,  cmb,   W1, b1, h1, DD, HH);
            // layer 2: [B,H] -> [B,H], relu
            gemm_bias_act<64, 64, true ><<<grdL2, thr1>>>(h1, cnone, W2, b2, h2, HH, HH);
            // layer 3: [B,H] -> [B,D]
            gemm_bias_act<32, 64, false><<<grdL3, thr3>>>(h2, cnone, W3, b3, k[s], HH, DD);
        }
        bool emit = ((step & 3) == 3);
        rk_finalize<<<BB * DD / 256, 256>>>(y, k[0], k[2], k[3], k[4], k[5],
                                            emit ? out : nullptr, step >> 2);
    }
}

// round 3
// speedup vs baseline: 2.7026x; 2.7026x over previous
#include <cuda_runtime.h>
#include <cstdint>
#include <cstddef>

// ---------------------------------------------------------------------------
// NeuralODE Dopri5, GEMMs via mma.sync m16n8k8 TF32 (3xTF32 split for fp32
// accuracy). tcgen05 unavailable: harness compiles at compute_103 (no 'a').
// RK combines fused into layer-3 epilogue; 18 launches per RK step.
// ---------------------------------------------------------------------------

#define BB 1024
#define DD 256
#define HH 512
#define N_STEPS 40
#define HSTEP 0.25f

__device__ float g_y   [BB * DD];
__device__ float g_ycmb[BB * DD];
__device__ float g_k [6][BB * DD];
__device__ float g_h1[BB * HH];
__device__ float g_h2[BB * HH];
__device__ float g_W1hi[HH * DD], g_W1lo[HH * DD];
__device__ float g_W2hi[HH * HH], g_W2lo[HH * HH];
__device__ float g_W3hi[DD * HH], g_W3lo[DD * HH];

struct Epi {
    const float* yin;
    const float* ks[4];
    float        cks[4];
    int          nks;
    float        cself;
    float*       aux;
    float*       emit;
    int          t;
};

// ----------------------------- helpers -------------------------------------
__device__ __forceinline__ uint32_t smem_u32(const void* p) {
    uint32_t a;
    asm("{ .reg .u64 t; cvta.to.shared.u64 t, %1; cvt.u32.u64 %0, t; }"
        : "=r"(a) : "l"(p));
    return a;
}
__device__ __forceinline__ void tf32split(float x, uint32_t& hi, uint32_t& lo) {
    uint32_t h; asm("cvt.rna.tf32.f32 %0, %1;" : "=r"(h) : "f"(x));
    float r = x - __uint_as_float(h);
    asm("cvt.rna.tf32.f32 %0, %1;" : "=r"(lo) : "f"(r));
    hi = h;
}
__device__ __forceinline__ uint32_t lds32(uint32_t a) {
    uint32_t v; asm volatile("ld.shared.b32 %0, [%1];" : "=r"(v) : "r"(a));
    return v;
}
__device__ __forceinline__ void sts128(uint32_t a, uint32_t x, uint32_t y,
                                       uint32_t z, uint32_t w) {
    asm volatile("st.shared.v4.b32 [%0], {%1,%2,%3,%4};"
                 :: "r"(a), "r"(x), "r"(y), "r"(z), "r"(w) : "memory");
}
__device__ __forceinline__ void cp16(uint32_t d, const float* s) {
    asm volatile("cp.async.cg.shared.global [%0], [%1], 16;"
                 :: "r"(d), "l"(s) : "memory");
}
__device__ __forceinline__ void mma8(float* d, const uint32_t* a,
                                     uint32_t b0, uint32_t b1) {
    asm volatile(
        "mma.sync.aligned.m16n8k8.row.col.f32.tf32.tf32.f32 "
        "{%0,%1,%2,%3}, {%4,%5,%6,%7}, {%8,%9}, {%0,%1,%2,%3};"
        : "+f"(d[0]), "+f"(d[1]), "+f"(d[2]), "+f"(d[3])
        : "r"(a[0]), "r"(a[1]), "r"(a[2]), "r"(a[3]), "r"(b0), "r"(b1));
}

// ---------------------------------------------------------------------------
// GEMM: C[M,N] = act(A[M,K] @ W[N,K]^T + bias).
// MT = m-tiles per warp (CTA rows = 32*MT). 256 threads, warp grid 2(M)x4(N),
// warp tile (16*MT) x 16. BK=32, double-buffered smem, XOR-swizzled layout:
// smem[row][col ^ (4*(row&7))] -> conflict-free STS.128 and fragment LDS.
// Buffer layout (bytes): Ahi 0 | Alo 8192 | Whi 16384 | Wlo 24576; stride 32768.
// MODE 0: relu store. MODE 1: linear store + fused RK-combine epilogue.
// ---------------------------------------------------------------------------
#define SMEM_BYTES 65536

template<int MT, int MODE>
__global__ __launch_bounds__(256, 1)
void gemm_tc(const float* __restrict__ A,
             const float* __restrict__ Whi, const float* __restrict__ Wlo,
             const float* __restrict__ bias, float* __restrict__ C,
             int K, int N, Epi ep)
{
    constexpr int BM = 32 * MT;
    extern __shared__ float smem[];
    const uint32_t sb = smem_u32(smem);
    const int tid  = threadIdx.x;
    const int warp = tid >> 5, lane = tid & 31;
    const int wM = warp >> 2, wN = warp & 3;
    const int g = lane >> 2, c = lane & 3;
    const int m0 = blockIdx.y * BM, n0 = blockIdx.x * 64;

    const int lr  = tid >> 3;            // 0..31
    const int lc4 = (tid & 7) * 4;
    const uint32_t scol   = (uint32_t)lc4 ^ (((uint32_t)lr & 7) << 2);
    const uint32_t storeA = sb + lr * 128 + scol * 4;
    const uint32_t storeW = sb + 16384 + lr * 128 + scol * 4;

    float4 pa[MT];
    const int S = K >> 5;

    auto ldA = [&](int s) {
        const float* ap = A + (size_t)(m0 + lr) * K + (s << 5) + lc4;
        #pragma unroll
        for (int q = 0; q < MT; q++)
            pa[q] = *(const float4*)(ap + (size_t)q * 32 * K);
    };
    auto cpW = [&](int s, int b) {
        const float* wh = Whi + (size_t)(n0 + lr) * K + (s << 5) + lc4;
        const float* wl = Wlo + (size_t)(n0 + lr) * K + (s << 5) + lc4;
        uint32_t d = storeW + b * 32768;
        #pragma unroll
        for (int q = 0; q < 2; q++) {
            cp16(d + q * 4096,        wh + (size_t)q * 32 * K);
            cp16(d + 8192 + q * 4096, wl + (size_t)q * 32 * K);
        }
        asm volatile("cp.async.commit_group;" ::: "memory");
    };
    auto stA = [&](int b) {
        uint32_t d = storeA + b * 32768;
        #pragma unroll
        for (int q = 0; q < MT; q++) {
            uint32_t hx, hy, hz, hw, lx, ly, lz, lw;
            tf32split(pa[q].x, hx, lx); tf32split(pa[q].y, hy, ly);
            tf32split(pa[q].z, hz, lz); tf32split(pa[q].w, hw, lw);
            sts128(d + q * 4096,        hx, hy, hz, hw);
            sts128(d + q * 4096 + 8192, lx, ly, lz, lw);
        }
    };

    float acc[MT][2][4];
    #pragma unroll
    for (int i = 0; i < MT; i++)
        #pragma unroll
        for (int nt = 0; nt < 2; nt++)
            #pragma unroll
            for (int q = 0; q < 4; q++) acc[i][nt][q] = 0.0f;

    const uint32_t swz = ((uint32_t)g) << 2;
    uint32_t aRow[MT][2], bRow[2];
    #pragma unroll
    for (int i = 0; i < MT; i++) {
        aRow[i][0] = (uint32_t)(wM * 16 * MT + i * 16 + g) * 128;
        aRow[i][1] = aRow[i][0] + 8 * 128;
    }
    #pragma unroll
    for (int nt = 0; nt < 2; nt++)
        bRow[nt] = (uint32_t)(wN * 16 + nt * 8 + g) * 128;

    ldA(0);
    cpW(0, 0);

    for (int s = 0; s < S; s++) {
        const int b = s & 1;
        stA(b);
        asm volatile("cp.async.wait_group 0;" ::: "memory");
        __syncthreads();
        if (s + 1 < S) { ldA(s + 1); cpW(s + 1, b ^ 1); }

        const uint32_t base = sb + b * 32768;
        #pragma unroll
        for (int j = 0; j < 4; j++) {
            const uint32_t ca0 = ((8u * j + c) ^ swz) * 4;
            const uint32_t ca1 = ((8u * j + c + 4) ^ swz) * 4;
            uint32_t ah[MT][4], al[MT][4];
            #pragma unroll
            for (int i = 0; i < MT; i++) {
                ah[i][0] = lds32(base + aRow[i][0] + ca0);
                ah[i][1] = lds32(base + aRow[i][1] + ca0);
                ah[i][2] = lds32(base + aRow[i][0] + ca1);
                ah[i][3] = lds32(base + aRow[i][1] + ca1);
                al[i][0] = lds32(base + 8192 + aRow[i][0] + ca0);
                al[i][1] = lds32(base + 8192 + aRow[i][1] + ca0);
                al[i][2] = lds32(base + 8192 + aRow[i][0] + ca1);
                al[i][3] = lds32(base + 8192 + aRow[i][1] + ca1);
            }
            #pragma unroll
            for (int nt = 0; nt < 2; nt++) {
                uint32_t bh0 = lds32(base + 16384 + bRow[nt] + ca0);
                uint32_t bh1 = lds32(base + 16384 + bRow[nt] + ca1);
                uint32_t bl0 = lds32(base + 24576 + bRow[nt] + ca0);
                uint32_t bl1 = lds32(base + 24576 + bRow[nt] + ca1);
                #pragma unroll
                for (int i = 0; i < MT; i++) {
                    mma8(acc[i][nt], ah[i], bh0, bh1);
                    mma8(acc[i][nt], ah[i], bl0, bl1);
                    mma8(acc[i][nt], al[i], bh0, bh1);
                }
            }
        }
    }

    // ---- epilogue ----
    #pragma unroll
    for (int i = 0; i < MT; i++) {
        #pragma unroll
        for (int nt = 0; nt < 2; nt++) {
            const int col  = n0 + wN * 16 + nt * 8 + 2 * c;
            const float b0v = bias[col], b1v = bias[col + 1];
            const int row0 = m0 + wM * 16 * MT + i * 16 + g;
            #pragma unroll
            for (int hh = 0; hh < 2; hh++) {
                const int row = row0 + 8 * hh;
                float v0 = acc[i][nt][2 * hh + 0] + b0v;
                float v1 = acc[i][nt][2 * hh + 1] + b1v;
                const size_t idx = (size_t)row * N + col;
                if (MODE == 0) {
                    v0 = fmaxf(v0, 0.0f); v1 = fmaxf(v1, 0.0f);
                    *(float2*)(C + idx) = make_float2(v0, v1);
                } else {
                    *(float2*)(C + idx) = make_float2(v0, v1);
                    float a0 = ep.yin[idx]     + ep.cself * v0;
                    float a1 = ep.yin[idx + 1] + ep.cself * v1;
                    for (int t = 0; t < ep.nks; t++) {
                        a0 += ep.cks[t] * ep.ks[t][idx];
                        a1 += ep.cks[t] * ep.ks[t][idx + 1];
                    }
                    *(float2*)(ep.aux + idx) = make_float2(a0, a1);
                    if (ep.emit) {
                        const size_t o = (size_t)row * (10 * DD) + (size_t)ep.t * DD + col;
                        *(float2*)(ep.emit + o) = make_float2(a0, a1);
                    }
                }
            }
        }
    }
}

// Split W into tf32 hi/lo parts (both tf32-rounded)
__global__ void wsplit_kernel(const float* __restrict__ W,
                              float* __restrict__ hi, float* __restrict__ lo, int n)
{
    int i = blockIdx.x * blockDim.x + threadIdx.x;
    if (i < n) {
        uint32_t h, l;
        tf32split(W[i], h, l);
        hi[i] = __uint_as_float(h);
        lo[i] = __uint_as_float(l);
    }
}

extern "C" void kernel_launch(void* const* d_in, const int* in_sizes, int n_in,
                              void* d_out, int out_size)
{
    (void)in_sizes; (void)n_in; (void)out_size;
    const float* x0 = (const float*)d_in[0];
    // d_in[1] is T (int32, always 11) — baked into the graph.
    const float* W1 = (const float*)d_in[2];
    const float* b1 = (const float*)d_in[3];
    const float* W2 = (const float*)d_in[4];
    const float* b2 = (const float*)d_in[5];
    const float* W3 = (const float*)d_in[6];
    const float* b3 = (const float*)d_in[7];
    float* out = (float*)d_out;

    float *y, *ycmb, *h1, *h2, *kbase;
    float *w1h, *w1l, *w2h, *w2l, *w3h, *w3l;
    cudaGetSymbolAddress((void**)&y,     g_y);
    cudaGetSymbolAddress((void**)&ycmb,  g_ycmb);
    cudaGetSymbolAddress((void**)&h1,    g_h1);
    cudaGetSymbolAddress((void**)&h2,    g_h2);
    cudaGetSymbolAddress((void**)&kbase, g_k);
    cudaGetSymbolAddress((void**)&w1h,   g_W1hi);
    cudaGetSymbolAddress((void**)&w1l,   g_W1lo);
    cudaGetSymbolAddress((void**)&w2h,   g_W2hi);
    cudaGetSymbolAddress((void**)&w2l,   g_W2lo);
    cudaGetSymbolAddress((void**)&w3h,   g_W3hi);
    cudaGetSymbolAddress((void**)&w3l,   g_W3lo);
    float* k[6];
    for (int j = 0; j < 6; j++) k[j] = kbase + (size_t)j * BB * DD;

    cudaFuncSetAttribute(gemm_tc<2, 0>, cudaFuncAttributeMaxDynamicSharedMemorySize, SMEM_BYTES);
    cudaFuncSetAttribute(gemm_tc<1, 1>, cudaFuncAttributeMaxDynamicSharedMemorySize, SMEM_BYTES);

    // y = x0[:,0,:]
    cudaMemcpyAsync(y, x0, sizeof(float) * BB * DD, cudaMemcpyDeviceToDevice);

    wsplit_kernel<<<(HH * DD + 255) / 256, 256>>>(W1, w1h, w1l, HH * DD);
    wsplit_kernel<<<(HH * HH + 255) / 256, 256>>>(W2, w2h, w2l, HH * HH);
    wsplit_kernel<<<(DD * HH + 255) / 256, 256>>>(W3, w3h, w3l, DD * HH);

    // Dopri5 tableau
    const double A2[] = {1.0/5.0};
    const double A3[] = {3.0/40.0, 9.0/40.0};
    const double A4[] = {44.0/45.0, -56.0/15.0, 32.0/9.0};
    const double A5[] = {19372.0/6561.0, -25360.0/2187.0, 64448.0/6561.0, -212.0/729.0};
    const double A6[] = {9017.0/3168.0, -355.0/33.0, 46732.0/5247.0, 49.0/176.0, -5103.0/18656.0};
    const double* Arows[5] = {A2, A3, A4, A5, A6};

    const dim3 grd1(HH / 64, BB / 64);   // 8 x 16 = 128 CTAs
    const dim3 grd2(HH / 64, BB / 64);   // 128 CTAs
    const dim3 grd3(DD / 64, BB / 32);   // 4 x 32 = 128 CTAs

    Epi enone = {};

    for (int step = 0; step < N_STEPS; step++) {
        for (int s = 0; s < 6; s++) {
            const float* Ain = (s == 0) ? y : ycmb;
            gemm_tc<2, 0><<<grd1, 256, SMEM_BYTES>>>(Ain, w1h, w1l, b1, h1, DD, HH, enone);
            gemm_tc<2, 0><<<grd2, 256, SMEM_BYTES>>>(h1,  w2h, w2l, b2, h2, HH, HH, enone);

            Epi ep = {};
            ep.yin = y;
            if (s < 5) {
                const double* row = Arows[s];
                ep.nks = s;
                for (int j = 0; j < s; j++) {
                    ep.ks[j]  = k[j];
                    ep.cks[j] = (float)((double)HSTEP * row[j]);
                }
                ep.cself = (float)((double)HSTEP * row[s]);
                ep.aux   = ycmb;
                ep.emit  = nullptr;
                ep.t     = 0;
            } else {
                ep.nks = 4;
                ep.ks[0] = k[0]; ep.cks[0] = (float)((double)HSTEP * (35.0 / 384.0));
                ep.ks[1] = k[2]; ep.cks[1] = (float)((double)HSTEP * (500.0 / 1113.0));
                ep.ks[2] = k[3]; ep.cks[2] = (float)((double)HSTEP * (125.0 / 192.0));
                ep.ks[3] = k[4]; ep.cks[3] = (float)((double)HSTEP * (-2187.0 / 6784.0));
                ep.cself = (float)((double)HSTEP * (11.0 / 84.0));
                ep.aux   = y;
                ep.emit  = ((step & 3) == 3) ? out : nullptr;
                ep.t     = step >> 2;
            }
            gemm_tc<1, 1><<<grd3, 256, SMEM_BYTES>>>(h2, w3h, w3l, b3, k[s], HH, DD, ep);
        }
    }
}

// round 4
// speedup vs baseline: 2.7129x; 1.0038x over previous
#include <cuda_runtime.h>
#include <cstdint>
#include <cstddef>

// ---------------------------------------------------------------------------
// NeuralODE Dopri5, GEMMs via mma.sync m16n8k8 TF32 (3xTF32 split) with
// ldmatrix fragment loads. RK combines fused into layer-3 epilogue.
// ---------------------------------------------------------------------------

#define BB 1024
#define DD 256
#define HH 512
#define N_STEPS 40
#define HSTEP 0.25f

__device__ float g_y   [BB * DD];
__device__ float g_ycmb[BB * DD];
__device__ float g_k [6][BB * DD];
__device__ float g_h1[BB * HH];
__device__ float g_h2[BB * HH];
__device__ float g_W1hi[HH * DD], g_W1lo[HH * DD];
__device__ float g_W2hi[HH * HH], g_W2lo[HH * HH];
__device__ float g_W3hi[DD * HH], g_W3lo[DD * HH];

struct Epi {
    const float* yin;
    const float* ks[4];
    float        cks[4];
    int          nks;
    float        cself;
    float*       aux;
    float*       emit;
    int          t;
};

// ----------------------------- helpers -------------------------------------
__device__ __forceinline__ uint32_t smem_u32(const void* p) {
    uint32_t a;
    asm("{ .reg .u64 t; cvta.to.shared.u64 t, %1; cvt.u32.u64 %0, t; }"
        : "=r"(a) : "l"(p));
    return a;
}
__device__ __forceinline__ void tf32split(float x, uint32_t& hi, uint32_t& lo) {
    uint32_t h; asm("cvt.rna.tf32.f32 %0, %1;" : "=r"(h) : "f"(x));
    float r = x - __uint_as_float(h);
    asm("cvt.rna.tf32.f32 %0, %1;" : "=r"(lo) : "f"(r));
    hi = h;
}
__device__ __forceinline__ void sts128(uint32_t a, uint32_t x, uint32_t y,
                                       uint32_t z, uint32_t w) {
    asm volatile("st.shared.v4.b32 [%0], {%1,%2,%3,%4};"
                 :: "r"(a), "r"(x), "r"(y), "r"(z), "r"(w) : "memory");
}
__device__ __forceinline__ void cp16(uint32_t d, const float* s) {
    asm volatile("cp.async.cg.shared.global [%0], [%1], 16;"
                 :: "r"(d), "l"(s) : "memory");
}
__device__ __forceinline__ void ldm4(uint32_t* r, uint32_t addr) {
    asm volatile("ldmatrix.sync.aligned.m8n8.x4.shared.b16 {%0,%1,%2,%3}, [%4];"
                 : "=r"(r[0]), "=r"(r[1]), "=r"(r[2]), "=r"(r[3]) : "r"(addr));
}
__device__ __forceinline__ void mma8(float* d, const uint32_t* a,
                                     uint32_t b0, uint32_t b1) {
    asm volatile(
        "mma.sync.aligned.m16n8k8.row.col.f32.tf32.tf32.f32 "
        "{%0,%1,%2,%3}, {%4,%5,%6,%7}, {%8,%9}, {%0,%1,%2,%3};"
        : "+f"(d[0]), "+f"(d[1]), "+f"(d[2]), "+f"(d[3])
        : "r"(a[0]), "r"(a[1]), "r"(a[2]), "r"(a[3]), "r"(b0), "r"(b1));
}

// ---------------------------------------------------------------------------
// GEMM: C[M,N] = act(A[M,K] @ W[N,K]^T + bias).
// 256 threads, warp grid 2(M)x4(N), warp tile (16*MT)x16, CTA tile (32*MT)x64.
// BK=32 double-buffered. Smem rows: 32 fp32 = 128B, XOR swizzle
// col_chunk ^= 4*(row&7) at 4-element granularity -> conflict-free STS.128,
// cp.async.16B, and ldmatrix gathers.
// Buffer (bytes): Ahi 0 | Alo 8192 | Whi 16384 | Wlo 24576; stride 32768.
// MODE 0: relu store. MODE 1: linear store + fused RK-combine epilogue.
// ---------------------------------------------------------------------------
#define SMEM_BYTES 65536

template<int MT, int MODE>
__global__ __launch_bounds__(256, 1)
void gemm_tc(const float* __restrict__ A,
             const float* __restrict__ Whi, const float* __restrict__ Wlo,
             const float* __restrict__ bias, float* __restrict__ C,
             int K, int N, Epi ep)
{
    constexpr int BM = 32 * MT;
    extern __shared__ float smem[];
    const uint32_t sb = smem_u32(smem);
    const int tid  = threadIdx.x;
    const int warp = tid >> 5, lane = tid & 31;
    const int wM = warp >> 2, wN = warp & 3;
    const int g = lane >> 2, c = lane & 3;
    const int m0 = blockIdx.y * BM, n0 = blockIdx.x * 64;

    // ---- staging addresses (stores) ----
    const int lr  = tid >> 3;            // 0..31
    const int lc4 = (tid & 7) * 4;
    const uint32_t scol   = (uint32_t)lc4 ^ (((uint32_t)lr & 7) << 2);
    const uint32_t storeA = sb + lr * 128 + scol * 4;
    const uint32_t storeW = sb + 16384 + lr * 128 + scol * 4;

    // ---- ldmatrix per-thread geometry ----
    const int quad = lane >> 3, l8 = lane & 7;
    // A: matrices {rows0-7 k0-3, rows8-15 k0-3, rows0-7 k4-7, rows8-15 k4-7}
    const int arow = ((quad & 1) << 3) + l8;       // row within m16 tile
    const uint32_t kcA = (uint32_t)((quad & 2) << 1);  // 0 or 4
    // B: matrices {nt0 k0-3, nt0 k4-7, nt1 k0-3, nt1 k4-7}
    const int brow = ((quad & 2) << 2) + l8;       // row within 16 n-rows
    const uint32_t kcB = (uint32_t)((quad & 1) << 2);  // 0 or 4

    uint32_t aoff[MT];
    #pragma unroll
    for (int i = 0; i < MT; i++)
        aoff[i] = (uint32_t)(wM * 16 * MT + i * 16 + arow) * 128;
    const uint32_t swzA = ((uint32_t)(arow & 7)) << 2;
    const uint32_t boff = (uint32_t)(wN * 16 + brow) * 128;
    const uint32_t swzB = ((uint32_t)(brow & 7)) << 2;

    float4 pa[MT];
    const int S = K >> 5;

    auto ldA = [&](int s) {
        const float* ap = A + (size_t)(m0 + lr) * K + (s << 5) + lc4;
        #pragma unroll
        for (int q = 0; q < MT; q++)
            pa[q] = *(const float4*)(ap + (size_t)q * 32 * K);
    };
    auto cpW = [&](int s, int b) {
        const float* wh = Whi + (size_t)(n0 + lr) * K + (s << 5) + lc4;
        const float* wl = Wlo + (size_t)(n0 + lr) * K + (s << 5) + lc4;
        uint32_t d = storeW + b * 32768;
        #pragma unroll
        for (int q = 0; q < 2; q++) {
            cp16(d + q * 4096,        wh + (size_t)q * 32 * K);
            cp16(d + 8192 + q * 4096, wl + (size_t)q * 32 * K);
        }
        asm volatile("cp.async.commit_group;" ::: "memory");
    };
    auto stA = [&](int b) {
        uint32_t d = storeA + b * 32768;
        #pragma unroll
        for (int q = 0; q < MT; q++) {
            uint32_t hx, hy, hz, hw, lx, ly, lz, lw;
            tf32split(pa[q].x, hx, lx); tf32split(pa[q].y, hy, ly);
            tf32split(pa[q].z, hz, lz); tf32split(pa[q].w, hw, lw);
            sts128(d + q * 4096,        hx, hy, hz, hw);
            sts128(d + q * 4096 + 8192, lx, ly, lz, lw);
        }
    };

    float acc[MT][2][4];
    #pragma unroll
    for (int i = 0; i < MT; i++)
        #pragma unroll
        for (int nt = 0; nt < 2; nt++)
            #pragma unroll
            for (int q = 0; q < 4; q++) acc[i][nt][q] = 0.0f;

    ldA(0);
    cpW(0, 0);

    for (int s = 0; s < S; s++) {
        const int b = s & 1;
        stA(b);
        asm volatile("cp.async.wait_group 0;" ::: "memory");
        __syncthreads();
        if (s + 1 < S) { ldA(s + 1); cpW(s + 1, b ^ 1); }

        const uint32_t base = sb + b * 32768;
        #pragma unroll
        for (int j = 0; j < 4; j++) {
            const uint32_t colA = (((8u * j) | kcA) ^ swzA) * 4;
            const uint32_t colB = (((8u * j) | kcB) ^ swzB) * 4;
            uint32_t ah[MT][4], al[MT][4], bh[4], bl[4];
            #pragma unroll
            for (int i = 0; i < MT; i++) {
                ldm4(ah[i], base + aoff[i] + colA);
                ldm4(al[i], base + 8192 + aoff[i] + colA);
            }
            ldm4(bh, base + 16384 + boff + colB);
            ldm4(bl, base + 24576 + boff + colB);
            #pragma unroll
            for (int nt = 0; nt < 2; nt++) {
                #pragma unroll
                for (int i = 0; i < MT; i++) {
                    mma8(acc[i][nt], ah[i], bh[2 * nt], bh[2 * nt + 1]);
                    mma8(acc[i][nt], ah[i], bl[2 * nt], bl[2 * nt + 1]);
                    mma8(acc[i][nt], al[i], bh[2 * nt], bh[2 * nt + 1]);
                }
            }
        }
    }

    // ---- epilogue ----
    #pragma unroll
    for (int i = 0; i < MT; i++) {
        #pragma unroll
        for (int nt = 0; nt < 2; nt++) {
            const int col  = n0 + wN * 16 + nt * 8 + 2 * c;
            const float b0v = bias[col], b1v = bias[col + 1];
            const int row0 = m0 + wM * 16 * MT + i * 16 + g;
            #pragma unroll
            for (int hh = 0; hh < 2; hh++) {
                const int row = row0 + 8 * hh;
                float v0 = acc[i][nt][2 * hh + 0] + b0v;
                float v1 = acc[i][nt][2 * hh + 1] + b1v;
                const size_t idx = (size_t)row * N + col;
                if (MODE == 0) {
                    v0 = fmaxf(v0, 0.0f); v1 = fmaxf(v1, 0.0f);
                    *(float2*)(C + idx) = make_float2(v0, v1);
                } else {
                    *(float2*)(C + idx) = make_float2(v0, v1);
                    float a0 = ep.yin[idx]     + ep.cself * v0;
                    float a1 = ep.yin[idx + 1] + ep.cself * v1;
                    for (int t = 0; t < ep.nks; t++) {
                        a0 += ep.cks[t] * ep.ks[t][idx];
                        a1 += ep.cks[t] * ep.ks[t][idx + 1];
                    }
                    *(float2*)(ep.aux + idx) = make_float2(a0, a1);
                    if (ep.emit) {
                        const size_t o = (size_t)row * (10 * DD) + (size_t)ep.t * DD + col;
                        *(float2*)(ep.emit + o) = make_float2(a0, a1);
                    }
                }
            }
        }
    }
}

// Split W into tf32 hi/lo parts (both tf32-rounded)
__global__ void wsplit_kernel(const float* __restrict__ W,
                              float* __restrict__ hi, float* __restrict__ lo, int n)
{
    int i = blockIdx.x * blockDim.x + threadIdx.x;
    if (i < n) {
        uint32_t h, l;
        tf32split(W[i], h, l);
        hi[i] = __uint_as_float(h);
        lo[i] = __uint_as_float(l);
    }
}

extern "C" void kernel_launch(void* const* d_in, const int* in_sizes, int n_in,
                              void* d_out, int out_size)
{
    (void)in_sizes; (void)n_in; (void)out_size;
    const float* x0 = (const float*)d_in[0];
    // d_in[1] is T (int32, always 11) — baked into the graph.
    const float* W1 = (const float*)d_in[2];
    const float* b1 = (const float*)d_in[3];
    const float* W2 = (const float*)d_in[4];
    const float* b2 = (const float*)d_in[5];
    const float* W3 = (const float*)d_in[6];
    const float* b3 = (const float*)d_in[7];
    float* out = (float*)d_out;

    float *y, *ycmb, *h1, *h2, *kbase;
    float *w1h, *w1l, *w2h, *w2l, *w3h, *w3l;
    cudaGetSymbolAddress((void**)&y,     g_y);
    cudaGetSymbolAddress((void**)&ycmb,  g_ycmb);
    cudaGetSymbolAddress((void**)&h1,    g_h1);
    cudaGetSymbolAddress((void**)&h2,    g_h2);
    cudaGetSymbolAddress((void**)&kbase, g_k);
    cudaGetSymbolAddress((void**)&w1h,   g_W1hi);
    cudaGetSymbolAddress((void**)&w1l,   g_W1lo);
    cudaGetSymbolAddress((void**)&w2h,   g_W2hi);
    cudaGetSymbolAddress((void**)&w2l,   g_W2lo);
    cudaGetSymbolAddress((void**)&w3h,   g_W3hi);
    cudaGetSymbolAddress((void**)&w3l,   g_W3lo);
    float* k[6];
    for (int j = 0; j < 6; j++) k[j] = kbase + (size_t)j * BB * DD;

    cudaFuncSetAttribute(gemm_tc<2, 0>, cudaFuncAttributeMaxDynamicSharedMemorySize, SMEM_BYTES);
    cudaFuncSetAttribute(gemm_tc<1, 1>, cudaFuncAttributeMaxDynamicSharedMemorySize, SMEM_BYTES);

    // y = x0[:,0,:]
    cudaMemcpyAsync(y, x0, sizeof(float) * BB * DD, cudaMemcpyDeviceToDevice);

    wsplit_kernel<<<(HH * DD + 255) / 256, 256>>>(W1, w1h, w1l, HH * DD);
    wsplit_kernel<<<(HH * HH + 255) / 256, 256>>>(W2, w2h, w2l, HH * HH);
    wsplit_kernel<<<(DD * HH + 255) / 256, 256>>>(W3, w3h, w3l, DD * HH);

    // Dopri5 tableau
    const double A2[] = {1.0/5.0};
    const double A3[] = {3.0/40.0, 9.0/40.0};
    const double A4[] = {44.0/45.0, -56.0/15.0, 32.0/9.0};
    const double A5[] = {19372.0/6561.0, -25360.0/2187.0, 64448.0/6561.0, -212.0/729.0};
    const double A6[] = {9017.0/3168.0, -355.0/33.0, 46732.0/5247.0, 49.0/176.0, -5103.0/18656.0};
    const double* Arows[5] = {A2, A3, A4, A5, A6};

    const dim3 grd1(HH / 64, BB / 64);   // 8 x 16 = 128 CTAs
    const dim3 grd2(HH / 64, BB / 64);   // 128 CTAs
    const dim3 grd3(DD / 64, BB / 32);   // 4 x 32 = 128 CTAs

    Epi enone = {};

    for (int step = 0; step < N_STEPS; step++) {
        for (int s = 0; s < 6; s++) {
            const float* Ain = (s == 0) ? y : ycmb;
            gemm_tc<2, 0><<<grd1, 256, SMEM_BYTES>>>(Ain, w1h, w1l, b1, h1, DD, HH, enone);
            gemm_tc<2, 0><<<grd2, 256, SMEM_BYTES>>>(h1,  w2h, w2l, b2, h2, HH, HH, enone);

            Epi ep = {};
            ep.yin = y;
            if (s < 5) {
                const double* row = Arows[s];
                ep.nks = s;
                for (int j = 0; j < s; j++) {
                    ep.ks[j]  = k[j];
                    ep.cks[j] = (float)((double)HSTEP * row[j]);
                }
                ep.cself = (float)((double)HSTEP * row[s]);
                ep.aux   = ycmb;
                ep.emit  = nullptr;
                ep.t     = 0;
            } else {
                ep.nks = 4;
                ep.ks[0] = k[0]; ep.cks[0] = (float)((double)HSTEP * (35.0 / 384.0));
                ep.ks[1] = k[2]; ep.cks[1] = (float)((double)HSTEP * (500.0 / 1113.0));
                ep.ks[2] = k[3]; ep.cks[2] = (float)((double)HSTEP * (125.0 / 192.0));
                ep.ks[3] = k[4]; ep.cks[3] = (float)((double)HSTEP * (-2187.0 / 6784.0));
                ep.cself = (float)((double)HSTEP * (11.0 / 84.0));
                ep.aux   = y;
                ep.emit  = ((step & 3) == 3) ? out : nullptr;
                ep.t     = step >> 2;
            }
            gemm_tc<1, 1><<<grd3, 256, SMEM_BYTES>>>(h2, w3h, w3l, b3, k[s], HH, DD, ep);
        }
    }
}